// round 11
// baseline (speedup 1.0000x reference)
#include <cuda_runtime.h>

// LSTM forward, GB300 sm_103a, full fp32 with packed fma.rn.f32x2 (FFMA2).
//
// Pipeline (all inside one graph-captured launch sequence):
//   1. zero_state        : reset h0, c0 (graph replays must be idempotent)
//   2. pack_weights      : interleave gates: packed col c = h*4 + g  (g: 0=i,1=f,2=c,3=o)
//   3. phase1_gemm       : GX[t][c][b] = emb[x[b,t]] @ Wxp + bias   (137 GFLOP, parallel)
//   4. lstm_step x 512   : G = GX_t + h@Whp ; elementwise -> c,h    (275 GFLOP, serial)
//   5. out_kernel        : out = h_final @ Why + by
//
// h is stored transposed hT[k][b] so the step kernel's SMEM staging is a flat
// contiguous copy and the a-operand LDS is a pure broadcast.

#define BATCH 64
#define TT    512
#define EMBD  512
#define HID   1024
#define G4    4096
#define NKT   16      // 1024 / 64 K-tiles in step kernel

typedef unsigned long long ull;

// ---------------- device scratch (static allocation only — harness rule) ---
__device__ float g_Wxp[EMBD * G4];                 //  8 MB  packed Wx
__device__ float g_Whp[HID  * G4];                 // 16 MB  packed Wh
__device__ float g_bp[G4];                         // packed bias
__device__ float g_GX[(size_t)TT * G4 * BATCH];    // 512 MB gates_x (+bias), [t][c][b]
__device__ float g_H0[HID * BATCH];                // hT ping
__device__ float g_H1[HID * BATCH];                // hT pong
__device__ float g_C [HID * BATCH];                // cT

// ---------------- packed fp32x2 helpers (Blackwell FFMA2, PTX-only) --------
__device__ __forceinline__ ull ffma2(ull a, ull b, ull c) {
    ull d;
    asm("fma.rn.f32x2 %0, %1, %2, %3;" : "=l"(d) : "l"(a), "l"(b), "l"(c));
    return d;
}
__device__ __forceinline__ ull pack2(float x, float y) {
    ull r;
    asm("mov.b64 %0, {%1, %2};" : "=l"(r) : "f"(x), "f"(y));
    return r;
}
__device__ __forceinline__ float2 unpack2(ull v) {
    float2 f;
    asm("mov.b64 {%0, %1}, %2;" : "=f"(f.x), "=f"(f.y) : "l"(v));
    return f;
}
__device__ __forceinline__ float sigmoidf_(float x) {
    return 1.0f / (1.0f + __expf(-x));
}

// ---------------- 1. zero state --------------------------------------------
__global__ void zero_state() {
    int i = blockIdx.x * blockDim.x + threadIdx.x;
    if (i < HID * BATCH) { g_H0[i] = 0.0f; g_C[i] = 0.0f; }
}

// ---------------- 2. pack weights: col c = h*4 + g -------------------------
__global__ void pack_weights(const float* Wxi, const float* Wxf, const float* Wxc, const float* Wxo,
                             const float* Whi, const float* Whf, const float* Whc, const float* Who,
                             const float* bi,  const float* bf,  const float* bc,  const float* bo) {
    const float* Wx[4] = {Wxi, Wxf, Wxc, Wxo};
    const float* Wh[4] = {Whi, Whf, Whc, Who};
    const float* bb[4] = {bi, bf, bc, bo};
    int stride = gridDim.x * blockDim.x;
    int tid0   = blockIdx.x * blockDim.x + threadIdx.x;
    for (int idx = tid0; idx < 4 * HID * HID; idx += stride) {
        int g = idx >> 20, r = idx & ((1 << 20) - 1);
        int k = r >> 10, h = r & 1023;
        g_Whp[k * G4 + (h << 2) + g] = Wh[g][r];
    }
    for (int idx = tid0; idx < 4 * EMBD * HID; idx += stride) {
        int g = idx >> 19, r = idx & ((1 << 19) - 1);
        int e = r >> 10, h = r & 1023;
        g_Wxp[e * G4 + (h << 2) + g] = Wx[g][r];
    }
    for (int idx = tid0; idx < G4; idx += stride) {
        int g = idx >> 10, h = idx & 1023;
        g_bp[(h << 2) + g] = bb[g][h];
    }
}

// ---------------- 3. phase-1 GEMM: GX = xe @ Wxp + b -----------------------
// Tile 128(M) x 64(N) x 32(K); 256 threads; micro-tile 8m x 4n; f32x2 lanes = m-pairs.
#define P1_BM 128
#define P1_BN 64
#define P1_BK 32
__global__ void __launch_bounds__(256) phase1_gemm(const int* xx, const float* emb) {
    __shared__ __align__(16) float As[P1_BK][P1_BM + 4];   // [k][m] transposed
    __shared__ __align__(16) float Bs[P1_BK][P1_BN];       // [k][n]
    __shared__ const float* rowp[P1_BM];

    int tid = threadIdx.x;
    int r0  = blockIdx.y * P1_BM;   // global row = t*64 + b
    int c0  = blockIdx.x * P1_BN;   // packed column

    if (tid < P1_BM) {
        int r = r0 + tid;
        int t = r >> 6, b = r & 63;
        rowp[tid] = emb + (size_t)xx[b * TT + t] * EMBD;
    }
    __syncthreads();

    int tx = tid & 15, ty = tid >> 4;     // n-quad, m-oct
    ull acc[4][4];
    #pragma unroll
    for (int p = 0; p < 4; p++)
        #pragma unroll
        for (int j = 0; j < 4; j++) acc[p][j] = 0ull;

    int lm = tid >> 1, lh = (tid & 1) * 16;   // A-load: row lm, k-half lh
    int bk = tid >> 3, bc = (tid & 7) * 4;    // B-load: row bk, col bc

    for (int k0 = 0; k0 < EMBD; k0 += P1_BK) {
        float4 av[4];
        const float* rp = rowp[lm] + k0 + lh;
        #pragma unroll
        for (int i = 0; i < 4; i++) av[i] = *(const float4*)(rp + 4 * i);
        float4 bv0 = *(const float4*)(g_Wxp + (size_t)(k0 + bk) * G4 + c0 + bc);
        float4 bv1 = *(const float4*)(g_Wxp + (size_t)(k0 + bk) * G4 + c0 + bc + 32);

        __syncthreads();   // previous tile fully consumed
        #pragma unroll
        for (int i = 0; i < 4; i++) {
            As[lh + 4 * i + 0][lm] = av[i].x;
            As[lh + 4 * i + 1][lm] = av[i].y;
            As[lh + 4 * i + 2][lm] = av[i].z;
            As[lh + 4 * i + 3][lm] = av[i].w;
        }
        *(float4*)&Bs[bk][bc]      = bv0;
        *(float4*)&Bs[bk][bc + 32] = bv1;
        __syncthreads();

        #pragma unroll
        for (int k = 0; k < P1_BK; k++) {
            ulonglong2 a01 = *(const ulonglong2*)&As[k][ty * 8];
            ulonglong2 a23 = *(const ulonglong2*)&As[k][ty * 8 + 4];
            float4 b4 = *(const float4*)&Bs[k][tx * 4];
            ull aav[4] = {a01.x, a01.y, a23.x, a23.y};
            ull bbv[4] = {pack2(b4.x, b4.x), pack2(b4.y, b4.y),
                          pack2(b4.z, b4.z), pack2(b4.w, b4.w)};
            #pragma unroll
            for (int p = 0; p < 4; p++)
                #pragma unroll
                for (int j = 0; j < 4; j++)
                    acc[p][j] = ffma2(aav[p], bbv[j], acc[p][j]);
        }
    }

    // epilogue: add bias, store GX[t][c][b] (b-pairs -> float2)
    float bpv[4];
    #pragma unroll
    for (int j = 0; j < 4; j++) bpv[j] = g_bp[c0 + tx * 4 + j];
    #pragma unroll
    for (int p = 0; p < 4; p++) {
        int m = ty * 8 + 2 * p;
        int r = r0 + m;
        int t = r >> 6, b = r & 63;
        float* base = g_GX + (size_t)t * (G4 * BATCH) + (size_t)(c0 + tx * 4) * BATCH + b;
        #pragma unroll
        for (int j = 0; j < 4; j++) {
            float2 v = unpack2(acc[p][j]);
            v.x += bpv[j]; v.y += bpv[j];
            *(float2*)(base + j * BATCH) = v;
        }
    }
}

// ---------------- 4. one LSTM step -----------------------------------------
// 128 CTAs; CTA cb owns packed cols c0=cb*32 == h-units [cb*8, cb*8+8) x 4 gates.
// Block 256 = (tx: col 0..31, ty: batch-oct 0..7). Double-buffered reg->smem pipeline.
__global__ void __launch_bounds__(256) lstm_step(int t) {
    __shared__ __align__(16) float hs[2][64 * 64];   // [k][b] tiles (flat copy of hT)
    __shared__ __align__(16) float ws[2][64 * 32];   // [k][c] tiles

    int tid = threadIdx.x;
    int tx = tid & 31, ty = tid >> 5;
    int b0 = ty * 8;
    int c0 = blockIdx.x * 32;
    int h0 = blockIdx.x * 8;

    const float* hin  = (t & 1) ? g_H1 : g_H0;
    float*       hout = (t & 1) ? g_H0 : g_H1;

    // acc = gx + bias (precomputed), lanes are b-pairs
    ull acc[4];
    {
        const float* gxp = g_GX + (size_t)t * (G4 * BATCH) + (size_t)(c0 + tx) * BATCH + b0;
        #pragma unroll
        for (int p = 0; p < 4; p++) acc[p] = *(const ull*)(gxp + 2 * p);
    }

    float4 hr[4], wr[2];
    int wk = tid >> 3, wc = (tid & 7) * 4;

    // preload tile 0
    #pragma unroll
    for (int j = 0; j < 4; j++) hr[j] = *(const float4*)(hin + tid * 4 + j * 1024);
    #pragma unroll
    for (int p = 0; p < 2; p++)
        wr[p] = *(const float4*)(g_Whp + (size_t)(wk + p * 32) * G4 + c0 + wc);
    #pragma unroll
    for (int j = 0; j < 4; j++) *(float4*)(hs[0] + tid * 4 + j * 1024) = hr[j];
    #pragma unroll
    for (int p = 0; p < 2; p++) *(float4*)(ws[0] + (wk + p * 32) * 32 + wc) = wr[p];
    __syncthreads();

    int cur = 0;
    for (int tile = 0; tile < NKT; ++tile) {
        if (tile < NKT - 1) {   // prefetch next tile into registers
            const float* hsrc = hin + (tile + 1) * (64 * 64);
            #pragma unroll
            for (int j = 0; j < 4; j++) hr[j] = *(const float4*)(hsrc + tid * 4 + j * 1024);
            #pragma unroll
            for (int p = 0; p < 2; p++)
                wr[p] = *(const float4*)(g_Whp + (size_t)((tile + 1) * 64 + wk + p * 32) * G4 + c0 + wc);
        }
        const float* hb = hs[cur];
        const float* wb = ws[cur];
        #pragma unroll
        for (int k = 0; k < 64; k++) {
            ulonglong2 a  = *(const ulonglong2*)(hb + k * 64 + b0);       // broadcast LDS
            ulonglong2 a2 = *(const ulonglong2*)(hb + k * 64 + b0 + 4);
            float w = wb[k * 32 + tx];
            ull ww = pack2(w, w);
            acc[0] = ffma2(a.x,  ww, acc[0]);
            acc[1] = ffma2(a.y,  ww, acc[1]);
            acc[2] = ffma2(a2.x, ww, acc[2]);
            acc[3] = ffma2(a2.y, ww, acc[3]);
        }
        if (tile < NKT - 1) {
            int nxt = cur ^ 1;   // disjoint from buffer being read -> single sync
            #pragma unroll
            for (int j = 0; j < 4; j++) *(float4*)(hs[nxt] + tid * 4 + j * 1024) = hr[j];
            #pragma unroll
            for (int p = 0; p < 2; p++) *(float4*)(ws[nxt] + (wk + p * 32) * 32 + wc) = wr[p];
            __syncthreads();
            cur = nxt;
        }
    }

    // gate exchange via smem (reuse hs[0]; last tile computed from hs[1])
    float* Gs = hs[0];                       // [32][66] padded, c-major
    #pragma unroll
    for (int p = 0; p < 4; p++) {
        float2 v = unpack2(acc[p]);
        *(float2*)(Gs + tx * 66 + b0 + 2 * p) = v;
    }
    __syncthreads();

    for (int ii = tid; ii < 512; ii += 256) {
        int hh = ii >> 6, b = ii & 63;
        float gi = Gs[(hh * 4 + 0) * 66 + b];
        float gf = Gs[(hh * 4 + 1) * 66 + b];
        float gc = Gs[(hh * 4 + 2) * 66 + b];
        float go = Gs[(hh * 4 + 3) * 66 + b];
        float iv = sigmoidf_(gi);
        float fv = sigmoidf_(gf);
        float gv = tanhf(gc);
        float ov = sigmoidf_(go);
        int off = (h0 + hh) * 64 + b;
        float c = fv * g_C[off] + iv * gv;
        g_C[off]  = c;
        hout[off] = ov * tanhf(c);
    }
}

// ---------------- 5. output projection: out = h @ Why + by -----------------
__global__ void out_kernel(const float* Why, const float* by, float* out) {
    __shared__ float red[256];
    int b = blockIdx.x >> 1, o = blockIdx.x & 1;
    float s = 0.0f;
    for (int k = threadIdx.x; k < HID; k += 256)
        s += g_H0[k * 64 + b] * Why[k * 2 + o];   // T=512 even -> final h in g_H0
    red[threadIdx.x] = s;
    __syncthreads();
    for (int st = 128; st > 0; st >>= 1) {
        if (threadIdx.x < st) red[threadIdx.x] += red[threadIdx.x + st];
        __syncthreads();
    }
    if (threadIdx.x == 0) out[b * 2 + o] = red[0] + by[o];
}

// ---------------- launch ----------------------------------------------------
extern "C" void kernel_launch(void* const* d_in, const int* in_sizes, int n_in,
                              void* d_out, int out_size) {
    const int*   x   = (const int*)  d_in[0];
    const float* emb = (const float*)d_in[1];
    const float* Wxi = (const float*)d_in[2];
    const float* Whi = (const float*)d_in[3];
    const float* bi  = (const float*)d_in[4];
    const float* Wxf = (const float*)d_in[5];
    const float* Whf = (const float*)d_in[6];
    const float* bf  = (const float*)d_in[7];
    const float* Wxc = (const float*)d_in[8];
    const float* Whc = (const float*)d_in[9];
    const float* bc  = (const float*)d_in[10];
    const float* Wxo = (const float*)d_in[11];
    const float* Who = (const float*)d_in[12];
    const float* bo  = (const float*)d_in[13];
    const float* Why = (const float*)d_in[14];
    const float* by  = (const float*)d_in[15];
    float* out = (float*)d_out;

    zero_state<<<256, 256>>>();
    pack_weights<<<2048, 256>>>(Wxi, Wxf, Wxc, Wxo, Whi, Whf, Whc, Who, bi, bf, bc, bo);

    dim3 g1(G4 / P1_BN, (TT * BATCH) / P1_BM);   // (64, 256)
    phase1_gemm<<<g1, 256>>>(x, emb);

    for (int t = 0; t < TT; ++t)
        lstm_step<<<128, 256>>>(t);

    out_kernel<<<128, 256>>>(Why, by, out);
}